// round 15
// baseline (speedup 1.0000x reference)
#include <cuda_runtime.h>
#include <cuda_pipeline_primitives.h>

// Problem constants
#define BB 128
#define JJ 17
#define YY 96
#define XX 72
#define YX (YY * XX)                 // 6912
#define NTOT (BB * JJ * YX)          // 15,040,512 elements per plane
#define N4 (NTOT / 4)                // 3,760,128 float4 chunks per plane
#define CPM (YX / 4)                 // 1728 chunks per m-index

#define NBLK 1184                    // 148 SMs * 8 blocks (2048 thr/SM, one wave)
#define NTHR 256
#define STRIDE (NBLK * NTHR)         // 303,104
#define KMAX 13                      // ceil(N4 / STRIDE)
#define STAGES 3

static __device__ float        g_acc   = 0.0f;  // self-resets via atom.exch
static __device__ unsigned int g_count = 0;     // self-resets via atom.inc wrap

__global__ void __launch_bounds__(NTHR, 8) regloss_reduce(
    const float* __restrict__ loc,
    const float* __restrict__ cord,
    const float* __restrict__ tw,
    float* __restrict__ out)
{
    const float* __restrict__ loc0 = loc;
    const float* __restrict__ loc1 = loc + NTOT;

    // Per-thread staging: thread t owns slot [s*NTHR + t] of each buffer.
    // Contiguous float4 per warp -> conflict-free STS/LDS.128.
    __shared__ float4 bufA[STAGES * NTHR];
    __shared__ float4 bufB[STAGES * NTHR];

    const int tid  = threadIdx.x;
    const int base = blockIdx.x * NTHR + tid;

    // ── Prologue: prefetch stages 0 .. STAGES-2 ──
    #pragma unroll
    for (int s = 0; s < STAGES - 1; ++s) {
        const int idx = base + s * STRIDE;
        if (idx < N4) {
            __pipeline_memcpy_async(&bufA[s * NTHR + tid], loc0 + 4 * (size_t)idx, 16);
            __pipeline_memcpy_async(&bufB[s * NTHR + tid], loc1 + 4 * (size_t)idx, 16);
        }
        __pipeline_commit();
    }

    float acc = 0.0f;
    #pragma unroll 1
    for (int k = 0; k < KMAX; ++k) {
        // Prefetch stage k+STAGES-1 (register-free deep MLP)
        const int pk = k + STAGES - 1;
        if (pk < KMAX) {
            const int pidx = base + pk * STRIDE;
            const int ps   = pk % STAGES;
            if (pidx < N4) {
                __pipeline_memcpy_async(&bufA[ps * NTHR + tid], loc0 + 4 * (size_t)pidx, 16);
                __pipeline_memcpy_async(&bufB[ps * NTHR + tid], loc1 + 4 * (size_t)pidx, 16);
            }
        }
        __pipeline_commit();
        __pipeline_wait_prior(STAGES - 1);   // stage k's copies complete (own-thread data)

        const int i = base + k * STRIDE;
        if (i < N4) {
            const int s  = k % STAGES;
            const float4 lx = bufA[s * NTHR + tid];
            const float4 ly = bufB[s * NTHR + tid];

            // m = (4i)/YX = i/1728 ; within-m: y = rem/18 rows of 4 chunks
            const int m   = i / CPM;
            const int rem = i - m * CPM;
            const int y   = rem / 18;          // XX/4 = 18 chunks per row
            const int x0  = (rem - y * 18) * 4;

            const float w  = __ldg(tw + m);              // warp-uniform, L1-hit
            const float cx = __ldg(cord + m);            // cord[0] flat index == m
            const float cy = __ldg(cord + JJ * BB + m);  // cord[1]

            // int32-truncated ground-truth shifts (toward zero == astype(int32))
            const float gy  = truncf((float)y - cy);
            const float gx0 = truncf((float)(x0 + 0) - cx);
            const float gx1 = truncf((float)(x0 + 1) - cx);
            const float gx2 = truncf((float)(x0 + 2) - cx);
            const float gx3 = truncf((float)(x0 + 3) - cx);

            float d;
            d = (lx.x - gx0) * w; acc = fmaf(d, d, acc);
            d = (lx.y - gx1) * w; acc = fmaf(d, d, acc);
            d = (lx.z - gx2) * w; acc = fmaf(d, d, acc);
            d = (lx.w - gx3) * w; acc = fmaf(d, d, acc);
            d = (ly.x - gy)  * w; acc = fmaf(d, d, acc);
            d = (ly.y - gy)  * w; acc = fmaf(d, d, acc);
            d = (ly.z - gy)  * w; acc = fmaf(d, d, acc);
            d = (ly.w - gy)  * w; acc = fmaf(d, d, acc);
        }
    }

    // ── Block tree reduction (deterministic within block) ──
    __shared__ float sm[NTHR];
    sm[tid] = acc;
    __syncthreads();
    #pragma unroll
    for (int s = NTHR / 2; s >= 32; s >>= 1) {
        if (tid < s) sm[tid] += sm[tid + s];
        __syncthreads();
    }
    if (tid < 32) {
        float v = sm[tid];
        #pragma unroll
        for (int off = 16; off > 0; off >>= 1)
            v += __shfl_down_sync(0xFFFFFFFFu, v, off);
        if (tid == 0) {
            const double scale = 0.5 / (double)NTOT;
            const float contrib = (float)((double)v * scale);

            float* accp = &g_acc;
            unsigned int* cntp = &g_count;

            // release-add: no fence, no L1 flush (unlike __threadfence)
            asm volatile("red.release.gpu.add.f32 [%0], %1;"
                         :: "l"(accp), "f"(contrib) : "memory");
            // release-inc orders this block's add before the count bump;
            // wraps NBLK-1 -> 0, self-resetting for the next graph replay.
            unsigned int old;
            asm volatile("atom.release.gpu.inc.u32 %0, [%1], %2;"
                         : "=r"(old) : "l"(cntp), "r"(NBLK - 1u) : "memory");
            if (old == NBLK - 1u) {
                // acquire-exchange: returns the complete sum and resets the
                // accumulator to 0 for the next replay.
                unsigned int bits;
                asm volatile("atom.acquire.gpu.exch.b32 %0, [%1], %2;"
                             : "=r"(bits) : "l"(accp), "r"(0u) : "memory");
                out[0] = __uint_as_float(bits);
            }
        }
    }
}

extern "C" void kernel_launch(void* const* d_in, const int* in_sizes, int n_in,
                              void* d_out, int out_size)
{
    const float* loc  = (const float*)d_in[0];   // (2, B, J, Y, X) fp32
    const float* cord = (const float*)d_in[1];   // (2, J, B) fp32
    const float* tw   = (const float*)d_in[2];   // (B, J, 1) fp32
    float* out = (float*)d_out;

    regloss_reduce<<<NBLK, NTHR>>>(loc, cord, tw, out);
}

// round 16
// speedup vs baseline: 1.0126x; 1.0126x over previous
#include <cuda_runtime.h>

// Problem constants
#define BB 128
#define JJ 17
#define YY 96
#define XX 72
#define YX (YY * XX)                 // 6912
#define NM (BB * JJ)                 // 2176 distinct m = b*J+j values
#define NTOT (NM * YX)               // 15,040,512 elements per plane
#define CPM (YX / 4)                 // 1728 float4 chunks per m
#define XC (XX / 4)                  // 18 chunks per row

#define NBLK NM                      // one block per m -> cord/tw hoisted
#define NTHR 128                     // 15 blocks/SM max -> one wave for 2176

static __device__ float        g_acc   = 0.0f;  // self-resets via atom.exch
static __device__ unsigned int g_count = 0;     // self-resets via atom.inc wrap

__global__ void __launch_bounds__(NTHR) regloss_reduce(
    const float* __restrict__ loc,
    const float* __restrict__ cord,
    const float* __restrict__ tw,
    float* __restrict__ out)
{
    const int tid = threadIdx.x;
    const int m   = blockIdx.x;                  // = b*J + j (flat, same for tw & cord)

    // Hoisted per-block scalars (warp-uniform, one load each)
    const float w  = __ldg(tw + m);
    const float cx = __ldg(cord + m);            // cord[0] flat index == m
    const float cy = __ldg(cord + NM + m);       // cord[1]
    const float w2 = w * w;

    const float4* __restrict__ loc0 = reinterpret_cast<const float4*>(loc)  + (size_t)m * CPM;
    const float4* __restrict__ loc1 = reinterpret_cast<const float4*>(loc + NTOT) + (size_t)m * CPM;

    // Unweighted sum of squares for this m; weight applied once at the end.
    float partial = 0.0f;
    for (int c = tid; c < CPM; c += NTHR) {
        const float4 lx = __ldcs(loc0 + c);      // streaming: read-once, evict-first
        const float4 ly = __ldcs(loc1 + c);

        const int y  = c / XC;                   // magic-mul
        const int x0 = (c - y * XC) * 4;

        // int32-truncated ground-truth shifts (toward zero == astype(int32))
        const float gy  = truncf((float)y - cy);
        const float gx0 = truncf((float)(x0 + 0) - cx);
        const float gx1 = truncf((float)(x0 + 1) - cx);
        const float gx2 = truncf((float)(x0 + 2) - cx);
        const float gx3 = truncf((float)(x0 + 3) - cx);

        float d;
        d = lx.x - gx0; partial = fmaf(d, d, partial);
        d = lx.y - gx1; partial = fmaf(d, d, partial);
        d = lx.z - gx2; partial = fmaf(d, d, partial);
        d = lx.w - gx3; partial = fmaf(d, d, partial);
        d = ly.x - gy;  partial = fmaf(d, d, partial);
        d = ly.y - gy;  partial = fmaf(d, d, partial);
        d = ly.z - gy;  partial = fmaf(d, d, partial);
        d = ly.w - gy;  partial = fmaf(d, d, partial);
    }
    const float acc = w2 * partial;              // weight factored out of the loop

    // ── Block tree reduction over 128 threads (deterministic within block) ──
    __shared__ float sm[NTHR];
    sm[tid] = acc;
    __syncthreads();
    #pragma unroll
    for (int s = NTHR / 2; s >= 32; s >>= 1) {
        if (tid < s) sm[tid] += sm[tid + s];
        __syncthreads();
    }
    if (tid < 32) {
        float v = sm[tid];
        #pragma unroll
        for (int off = 16; off > 0; off >>= 1)
            v += __shfl_down_sync(0xFFFFFFFFu, v, off);
        if (tid == 0) {
            const double scale = 0.5 / (double)NTOT;
            const float contrib = (float)((double)v * scale);

            float* accp = &g_acc;
            unsigned int* cntp = &g_count;

            // release-add: no fence, no L1 flush (unlike __threadfence)
            asm volatile("red.release.gpu.add.f32 [%0], %1;"
                         :: "l"(accp), "f"(contrib) : "memory");
            // release-inc orders this block's add before the count bump;
            // wraps NBLK-1 -> 0, self-resetting for the next graph replay.
            unsigned int old;
            asm volatile("atom.release.gpu.inc.u32 %0, [%1], %2;"
                         : "=r"(old) : "l"(cntp), "r"(NBLK - 1u) : "memory");
            if (old == NBLK - 1u) {
                // acquire-exchange: returns the complete sum and resets the
                // accumulator to 0 for the next replay.
                unsigned int bits;
                asm volatile("atom.acquire.gpu.exch.b32 %0, [%1], %2;"
                             : "=r"(bits) : "l"(accp), "r"(0u) : "memory");
                out[0] = __uint_as_float(bits);
            }
        }
    }
}

extern "C" void kernel_launch(void* const* d_in, const int* in_sizes, int n_in,
                              void* d_out, int out_size)
{
    const float* loc  = (const float*)d_in[0];   // (2, B, J, Y, X) fp32
    const float* cord = (const float*)d_in[1];   // (2, J, B) fp32
    const float* tw   = (const float*)d_in[2];   // (B, J, 1) fp32
    float* out = (float*)d_out;

    regloss_reduce<<<NBLK, NTHR>>>(loc, cord, tw, out);
}

// round 17
// speedup vs baseline: 1.0594x; 1.0462x over previous
#include <cuda_runtime.h>

// Problem constants
#define BB 128
#define JJ 17
#define YY 96
#define XX 72
#define YX (YY * XX)                 // 6912
#define NM (BB * JJ)                 // 2176
#define NTOT (NM * YX)               // 15,040,512 elements per plane
#define N4 (NTOT / 4)                // 3,760,128 float4 chunks per plane
#define CPM (YX / 4)                 // 1728 chunks per m
#define XC (XX / 4)                  // 18 chunks per row

#define NBLK 1184                    // 148 SMs * 8 blocks (2048 thr/SM, one wave)
#define NTHR 256
#define STRIDE (NBLK * NTHR)         // 303,104 = 175*1728 + 704
#define DM (STRIDE / CPM)            // 175
#define DR (STRIDE % CPM)            // 704

static __device__ float        g_acc   = 0.0f;  // self-resets via atom.exch
static __device__ unsigned int g_count = 0;     // self-resets via atom.inc wrap

__global__ void __launch_bounds__(NTHR) regloss_reduce(
    const float* __restrict__ loc,
    const float* __restrict__ cord,
    const float* __restrict__ tw,
    float* __restrict__ out)
{
    const float4* __restrict__ loc0 = reinterpret_cast<const float4*>(loc);
    const float4* __restrict__ loc1 = reinterpret_cast<const float4*>(loc + NTOT);

    const int tid  = threadIdx.x;
    const int base = blockIdx.x * NTHR + tid;

    // Incrementally-maintained (m, rem) decomposition of i: i = m*CPM + rem.
    // Eliminates all divides by CPM from the loop.
    int m   = base / CPM;            // one divide at entry only
    int rem = base - m * CPM;

    float acc = 0.0f;
    for (int i = base; i < N4; i += STRIDE) {
        const float4 lx = __ldcs(loc0 + i);      // streaming: read-once, evict-first
        const float4 ly = __ldcs(loc1 + i);

        const int y  = rem / XC;                 // single magic-mul
        const int x0 = (rem - y * XC) * 4;

        const float w  = __ldg(tw + m);              // L1-hit scalars
        const float cx = __ldg(cord + m);            // cord[0] flat index == m
        const float cy = __ldg(cord + NM + m);       // cord[1]

        // int32-truncated ground-truth shifts (toward zero == astype(int32))
        const float gy  = truncf((float)y - cy);
        const float gx0 = truncf((float)(x0 + 0) - cx);
        const float gx1 = truncf((float)(x0 + 1) - cx);
        const float gx2 = truncf((float)(x0 + 2) - cx);
        const float gx3 = truncf((float)(x0 + 3) - cx);

        float d;
        d = (lx.x - gx0) * w; acc = fmaf(d, d, acc);
        d = (lx.y - gx1) * w; acc = fmaf(d, d, acc);
        d = (lx.z - gx2) * w; acc = fmaf(d, d, acc);
        d = (lx.w - gx3) * w; acc = fmaf(d, d, acc);
        d = (ly.x - gy)  * w; acc = fmaf(d, d, acc);
        d = (ly.y - gy)  * w; acc = fmaf(d, d, acc);
        d = (ly.z - gy)  * w; acc = fmaf(d, d, acc);
        d = (ly.w - gy)  * w; acc = fmaf(d, d, acc);

        // Advance (m, rem) by STRIDE: m += 175, rem += 704, carry once.
        m   += DM;
        rem += DR;
        if (rem >= CPM) { rem -= CPM; ++m; }
    }

    // ── Block tree reduction (deterministic within block) ──
    __shared__ float sm[NTHR];
    sm[tid] = acc;
    __syncthreads();
    #pragma unroll
    for (int s = NTHR / 2; s >= 32; s >>= 1) {
        if (tid < s) sm[tid] += sm[tid + s];
        __syncthreads();
    }
    if (tid < 32) {
        float v = sm[tid];
        #pragma unroll
        for (int off = 16; off > 0; off >>= 1)
            v += __shfl_down_sync(0xFFFFFFFFu, v, off);
        if (tid == 0) {
            const double scale = 0.5 / (double)NTOT;
            const float contrib = (float)((double)v * scale);

            float* accp = &g_acc;
            unsigned int* cntp = &g_count;

            // release-add: no fence, no L1 flush (unlike __threadfence)
            asm volatile("red.release.gpu.add.f32 [%0], %1;"
                         :: "l"(accp), "f"(contrib) : "memory");
            // release-inc orders this block's add before the count bump;
            // wraps NBLK-1 -> 0, self-resetting for the next graph replay.
            unsigned int old;
            asm volatile("atom.release.gpu.inc.u32 %0, [%1], %2;"
                         : "=r"(old) : "l"(cntp), "r"(NBLK - 1u) : "memory");
            if (old == NBLK - 1u) {
                // acquire-exchange: returns the complete sum and resets the
                // accumulator to 0 for the next replay.
                unsigned int bits;
                asm volatile("atom.acquire.gpu.exch.b32 %0, [%1], %2;"
                             : "=r"(bits) : "l"(accp), "r"(0u) : "memory");
                out[0] = __uint_as_float(bits);
            }
        }
    }
}

extern "C" void kernel_launch(void* const* d_in, const int* in_sizes, int n_in,
                              void* d_out, int out_size)
{
    const float* loc  = (const float*)d_in[0];   // (2, B, J, Y, X) fp32
    const float* cord = (const float*)d_in[1];   // (2, J, B) fp32
    const float* tw   = (const float*)d_in[2];   // (B, J, 1) fp32
    float* out = (float*)d_out;

    regloss_reduce<<<NBLK, NTHR>>>(loc, cord, tw, out);
}